// round 6
// baseline (speedup 1.0000x reference)
#include <cuda_runtime.h>
#include <cuda_fp16.h>
#include <cstdint>

// ============================================================================
// out = LayerNorm(relu(x @ (m*W_v + (1-m)*W_r)))   [attention path is identity:
// softmax rows sum to 1 and the reference einsum contracts the softmax axis]
//   x: [131072, 256] f32,  W: [256, 512] f32,  out: [131072, 512] f32
// R6: fp16 mma.sync, KC=32, 4-stage cp.async ring, prefetch distance 3
// (wait_group 2 retires a group committed 3 chunks ago -> no exposed latency).
// CTA = 64 rows x 512 cols (LayerNorm CTA-local), 16 warps.
// ============================================================================

static constexpr int K_DIM  = 256;
static constexpr int N_DIM  = 512;
static constexpr int BM     = 64;
static constexpr int KC     = 32;
static constexpr int NCH    = K_DIM / KC;  // 8
static constexpr int M_TOT  = 2048 * 64;   // 131072
static constexpr int NT     = 512;         // 16 warps: wm = w>>3, wn = w&7

// SMEM layout (bytes)
static constexpr int SM_B  = 0;            // 4 stages x 32 KB (packed 2 n-rows / 128B line)
static constexpr int SM_A  = 131072;       // 4 stages x 8 KB (64 rows x 128B, 64B used)
static constexpr int SM_GB = 163840;       // gamma[512]+beta[512] f32 = 4 KB
static constexpr int SM_PS = 167936;       // psum[64][8]+psq[64][8]+stats[64][2] = 4.5 KB
static constexpr int SMEM_TOTAL = 172544;

// Pre-swizzled fp16 B chunk images (exact smem stage byte layout):
// off(n, kk) = swz((n>>1)*128 + (n&1)*64 + kk*2), kk = k % 32, chunk = k / 32.
__device__ __align__(16) unsigned char g_Bimg[NCH][32768];

// ---------------------------------------------------------------------------
__device__ __forceinline__ uint32_t smem_u32(const void* p) {
    uint32_t r;
    asm("{ .reg .u64 t; cvta.to.shared.u64 t, %1; cvt.u32.u64 %0, t; }" : "=r"(r) : "l"(p));
    return r;
}
__host__ __device__ __forceinline__ uint32_t swz(uint32_t o) { return o ^ ((o >> 3) & 0x70); }

__device__ __forceinline__ void cp16(uint32_t d, const void* s) {
    asm volatile("cp.async.cg.shared.global [%0], [%1], 16;" :: "r"(d), "l"(s));
}
__device__ __forceinline__ void cp_commit() { asm volatile("cp.async.commit_group;"); }
__device__ __forceinline__ void cp_wait2()  { asm volatile("cp.async.wait_group 2;"); }

__device__ __forceinline__ void ldsm4(uint32_t* r, uint32_t a) {
    asm volatile("ldmatrix.sync.aligned.m8n8.x4.shared.b16 {%0,%1,%2,%3}, [%4];"
                 : "=r"(r[0]), "=r"(r[1]), "=r"(r[2]), "=r"(r[3]) : "r"(a));
}
__device__ __forceinline__ void hmma(float* c, const uint32_t* a, const uint32_t* b) {
    asm volatile("mma.sync.aligned.m16n8k16.row.col.f32.f16.f16.f32 "
                 "{%0,%1,%2,%3},{%4,%5,%6,%7},{%8,%9},{%0,%1,%2,%3};"
                 : "+f"(c[0]), "+f"(c[1]), "+f"(c[2]), "+f"(c[3])
                 : "r"(a[0]), "r"(a[1]), "r"(a[2]), "r"(a[3]), "r"(b[0]), "r"(b[1]));
}

// ---------------------------------------------------------------------------
// Prep: W_c = m*W_v + (1-m)*W_r -> fp16, pre-swizzled packed chunk images.
// ---------------------------------------------------------------------------
__global__ void prep_kernel(const float* __restrict__ Wv, const float* __restrict__ Wr,
                            const float* __restrict__ mix) {
    int gid = blockIdx.x * blockDim.x + threadIdx.x;
    if (gid >= K_DIM * N_DIM) return;
    int n = gid & 511;
    int k = gid >> 9;
    float m = 1.0f / (1.0f + expf(-mix[0]));
    float w = m * Wv[k * N_DIM + n] + (1.0f - m) * Wr[k * N_DIM + n];
    int c  = k >> 5;
    int kk = k & 31;
    uint32_t off = swz((uint32_t)((n >> 1) * 128 + (n & 1) * 64 + kk * 2));
    *(__half*)(&g_Bimg[c][off]) = __float2half(w);
}

// ---------------------------------------------------------------------------
// Fused GEMM (fp16 mma.sync) + relu + full-width LayerNorm(512)
// ---------------------------------------------------------------------------
__global__ void __launch_bounds__(NT, 1)
gemm_ln_kernel(const float* __restrict__ x, const float* __restrict__ gamma,
               const float* __restrict__ beta, float* __restrict__ out) {
    extern __shared__ char smem[];
    const uint32_t sb = smem_u32(smem);
    const int tid  = threadIdx.x;
    const int warp = tid >> 5;
    const int lane = tid & 31;
    const int wm   = warp >> 3;   // 0..1 -> 32-row half
    const int wn   = warp & 7;    // 0..7 -> 64-col slice

    const size_t m0 = (size_t)blockIdx.x * BM;

    // gamma/beta into smem
    {
        float* gsh = (float*)(smem + SM_GB);
        for (int i = tid; i < N_DIM; i += NT) {
            gsh[i]         = gamma[i];
            gsh[N_DIM + i] = beta[i];
        }
    }

    // per-lane ldmatrix base offsets (KC=32 packed layouts, verified in R4)
    const uint32_t arow = (uint32_t)((wm * 32 + (lane & 15)) * 128 + (lane >> 4) * 16);
    const int nb = wn * 64 + ((lane >> 4) & 1) * 8 + (lane & 7);
    const uint32_t brow = (uint32_t)((nb >> 1) * 128 + (nb & 1) * 64 + ((lane >> 3) & 1) * 16);

    float acc[2][8][4];
    #pragma unroll
    for (int mt = 0; mt < 2; mt++)
        #pragma unroll
        for (int nt = 0; nt < 8; nt++)
            #pragma unroll
            for (int i = 0; i < 4; i++) acc[mt][nt][i] = 0.0f;

    // A indexing: chunk = 64 rows x 32 f32 = 512 float4; 1 per thread
    const int ar = tid >> 3;              // 0..63
    const int as = tid & 7;               // 0..7
    const uint32_t aso = swz((uint32_t)(ar * 128 + as * 8));
    const float* xrow = x + (m0 + ar) * K_DIM + as * 4;

    // ---- prologue: chunks 0..2 -> smem (B cp.async w/ per-chunk commit, A STS) ----
    #pragma unroll
    for (int p = 0; p < 3; p++) {
        #pragma unroll
        for (int i = 0; i < 4; i++) {
            int j = tid + i * NT;          // 0..2047
            cp16(sb + SM_B + p * 32768 + j * 16, &g_Bimg[p][j * 16]);
        }
        cp_commit();
        float4 v = *(const float4*)(xrow + p * KC);
        __half2 h01 = __floats2half2_rn(v.x, v.y);
        __half2 h23 = __floats2half2_rn(v.z, v.w);
        *(uint2*)(smem + SM_A + p * 8192 + aso) = make_uint2(*(uint32_t*)&h01, *(uint32_t*)&h23);
    }
    // prefetch A chunk 3 into regs
    float4 av = *(const float4*)(xrow + 3 * KC);

    // ---- main loop: prefetch distance 3 ----
    #pragma unroll
    for (int c = 0; c < NCH; c++) {
        const int stage = c & 3;
        cp_wait2();          // retires chunk c's group (committed 3 chunks ago)
        __syncthreads();     // chunk c visible to all; all warps done reading chunk c-1

        if (c < NCH - 3) {
            const int pst = (c + 3) & 3;   // = (c-1)&3, safe after barrier
            // STS A chunk c+3 from prefetched regs
            __half2 h01 = __floats2half2_rn(av.x, av.y);
            __half2 h23 = __floats2half2_rn(av.z, av.w);
            *(uint2*)(smem + SM_A + pst * 8192 + aso) =
                make_uint2(*(uint32_t*)&h01, *(uint32_t*)&h23);
            // LDG A chunk c+4
            if (c < NCH - 4) av = *(const float4*)(xrow + (c + 4) * KC);
            // B chunk c+3 cp.async (overlaps with MMA of chunks c..c+2)
            #pragma unroll
            for (int i = 0; i < 4; i++) {
                int j = tid + i * NT;
                cp16(sb + SM_B + pst * 32768 + j * 16, &g_Bimg[c + 3][j * 16]);
            }
        }
        cp_commit();         // always commit (possibly empty) to keep group accounting uniform

        // ---- MMA on chunk c: 2 k-steps ----
        const uint32_t Ab = sb + SM_A + stage * 8192;
        const uint32_t Bb = sb + SM_B + stage * 32768;
        uint32_t af[2][2][4];
        #pragma unroll
        for (int mt = 0; mt < 2; mt++)
            ldsm4(af[0][mt], Ab + swz(arow + mt * 2048));
        #pragma unroll
        for (int ks = 0; ks < 2; ks++) {
            const int cur = ks & 1;
            if (ks == 0)
                #pragma unroll
                for (int mt = 0; mt < 2; mt++)
                    ldsm4(af[1][mt], Ab + swz(arow + mt * 2048 + 32));
            #pragma unroll
            for (int bt = 0; bt < 4; bt++) {
                uint32_t bh[4];
                ldsm4(bh, Bb + swz(brow + bt * 1024 + ks * 32));
                #pragma unroll
                for (int mt = 0; mt < 2; mt++) {
                    hmma(acc[mt][2 * bt],     af[cur][mt], &bh[0]);
                    hmma(acc[mt][2 * bt + 1], af[cur][mt], &bh[2]);
                }
            }
        }
    }

    // ------------------- Epilogue: relu + LayerNorm(512) -------------------
    float* psum  = (float*)(smem + SM_PS);   // [64][8]
    float* psq   = psum + 512;               // [64][8]
    float* stats = psq + 512;                // [64][2]

    #pragma unroll
    for (int mt = 0; mt < 2; mt++) {
        #pragma unroll
        for (int half = 0; half < 2; half++) {
            float s = 0.0f, q = 0.0f;
            #pragma unroll
            for (int nt = 0; nt < 8; nt++) {
                float v0 = fmaxf(acc[mt][nt][half * 2 + 0], 0.0f);
                float v1 = fmaxf(acc[mt][nt][half * 2 + 1], 0.0f);
                s += v0 + v1;
                q += v0 * v0 + v1 * v1;
            }
            s += __shfl_xor_sync(0xFFFFFFFFu, s, 1);
            q += __shfl_xor_sync(0xFFFFFFFFu, q, 1);
            s += __shfl_xor_sync(0xFFFFFFFFu, s, 2);
            q += __shfl_xor_sync(0xFFFFFFFFu, q, 2);
            if ((lane & 3) == 0) {
                int r = wm * 32 + mt * 16 + (lane >> 2) + half * 8;
                psum[r * 8 + wn] = s;
                psq[r * 8 + wn]  = q;
            }
        }
    }
    __syncthreads();
    if (tid < BM) {
        float st = 0.0f, qt = 0.0f;
        #pragma unroll
        for (int i = 0; i < 8; i++) { st += psum[tid * 8 + i]; qt += psq[tid * 8 + i]; }
        float mean = st * (1.0f / 512.0f);
        float var  = qt * (1.0f / 512.0f) - mean * mean;
        stats[tid * 2]     = mean;
        stats[tid * 2 + 1] = rsqrtf(var + 1e-5f);
    }
    __syncthreads();

    const float* gsh = (const float*)(smem + SM_GB);
    const float* bsh = gsh + N_DIM;
    #pragma unroll
    for (int mt = 0; mt < 2; mt++) {
        #pragma unroll
        for (int half = 0; half < 2; half++) {
            int r = wm * 32 + mt * 16 + (lane >> 2) + half * 8;
            float mean = stats[r * 2];
            float rstd = stats[r * 2 + 1];
            float* orow = out + (size_t)(m0 + r) * N_DIM;
            #pragma unroll
            for (int nt = 0; nt < 8; nt++) {
                int col = wn * 64 + nt * 8 + (lane & 3) * 2;
                float2 o;
                o.x = (fmaxf(acc[mt][nt][half * 2 + 0], 0.0f) - mean) * rstd * gsh[col]     + bsh[col];
                o.y = (fmaxf(acc[mt][nt][half * 2 + 1], 0.0f) - mean) * rstd * gsh[col + 1] + bsh[col + 1];
                *(float2*)(orow + col) = o;
            }
        }
    }
}

// ---------------------------------------------------------------------------
// Host launcher. Inputs: x, W_q, W_k, W_v, W_r, mix, gamma, beta
// ---------------------------------------------------------------------------
extern "C" void kernel_launch(void* const* d_in, const int* in_sizes, int n_in,
                              void* d_out, int out_size) {
    const float* x     = (const float*)d_in[0];
    const float* Wv    = (const float*)d_in[3];
    const float* Wr    = (const float*)d_in[4];
    const float* mix   = (const float*)d_in[5];
    const float* gamma = (const float*)d_in[6];
    const float* beta  = (const float*)d_in[7];
    float* out = (float*)d_out;

    cudaFuncSetAttribute(gemm_ln_kernel, cudaFuncAttributeMaxDynamicSharedMemorySize, SMEM_TOTAL);

    prep_kernel<<<(K_DIM * N_DIM + 255) / 256, 256>>>(Wv, Wr, mix);
    gemm_ln_kernel<<<M_TOT / BM, NT, SMEM_TOTAL>>>(x, gamma, beta, out);
}

// round 7
// speedup vs baseline: 1.0026x; 1.0026x over previous
#include <cuda_runtime.h>
#include <cuda_fp16.h>
#include <cstdint>

// ============================================================================
// out = LayerNorm(relu(x @ (m*W_v + (1-m)*W_r)))   [attention path is identity:
// softmax rows sum to 1 and the reference einsum contracts the softmax axis]
//   x: [131072, 256] f32,  W: [256, 512] f32,  out: [131072, 512] f32
// R7: persistent CTAs (atomic tile stealing) with RESIDENT B: weight chunks
// 0..2 live in smem for the CTA's lifetime (loaded once), chunks 3..7 stream
// through a 3-stage cp.async ring. Cuts per-tile LSU ops ~20% and removes all
// per-tile B prologue latency. fp16 mma.sync, CTA tile = 64 rows x 512 cols.
// ============================================================================

static constexpr int K_DIM  = 256;
static constexpr int N_DIM  = 512;
static constexpr int BM     = 64;
static constexpr int KC     = 32;
static constexpr int NCH    = K_DIM / KC;   // 8
static constexpr int NTILES = 131072 / BM;  // 2048
static constexpr int NT     = 512;          // 16 warps
static constexpr int GRID   = 152;          // ~1 CTA per SM (GB300: 152 SMs)
static constexpr int NRES   = 3;            // resident B chunks 0..2

// SMEM layout (bytes)
static constexpr int SM_BRES = 0;           // 3 x 32768 = 96 KB (chunks 0..2, persistent)
static constexpr int SM_BSTR = 98304;       // 3 x 32768 = 96 KB (stream ring, chunks 3..7)
static constexpr int SM_A    = 196608;      // 2 x 8192 (A double buffer)
static constexpr int SM_GB   = 212992;      // gamma[512]+beta[512] f32 = 4 KB
static constexpr int SM_PS   = 217088;      // psum[64][8]+psq[64][8]+stats[64][2] = 4608
static constexpr int SM_T    = 221696;      // tile-index broadcast slot
static constexpr int SMEM_TOTAL = 221712;

// Pre-swizzled fp16 B chunk images (exact smem byte layout):
// off(n, kk) = swz((n>>1)*128 + (n&1)*64 + kk*2), kk = k % 32, chunk = k / 32.
__device__ __align__(16) unsigned char g_Bimg[NCH][32768];
__device__ int g_counter;

// ---------------------------------------------------------------------------
__device__ __forceinline__ uint32_t smem_u32(const void* p) {
    uint32_t r;
    asm("{ .reg .u64 t; cvta.to.shared.u64 t, %1; cvt.u32.u64 %0, t; }" : "=r"(r) : "l"(p));
    return r;
}
__host__ __device__ __forceinline__ uint32_t swz(uint32_t o) { return o ^ ((o >> 3) & 0x70); }

__device__ __forceinline__ void cp16(uint32_t d, const void* s) {
    asm volatile("cp.async.cg.shared.global [%0], [%1], 16;" :: "r"(d), "l"(s));
}
__device__ __forceinline__ void cp_commit() { asm volatile("cp.async.commit_group;"); }
template <int N>
__device__ __forceinline__ void cp_wait() { asm volatile("cp.async.wait_group %0;" :: "n"(N)); }

__device__ __forceinline__ void ldsm4(uint32_t* r, uint32_t a) {
    asm volatile("ldmatrix.sync.aligned.m8n8.x4.shared.b16 {%0,%1,%2,%3}, [%4];"
                 : "=r"(r[0]), "=r"(r[1]), "=r"(r[2]), "=r"(r[3]) : "r"(a));
}
__device__ __forceinline__ void hmma(float* c, const uint32_t* a, const uint32_t* b) {
    asm volatile("mma.sync.aligned.m16n8k16.row.col.f32.f16.f16.f32 "
                 "{%0,%1,%2,%3},{%4,%5,%6,%7},{%8,%9},{%0,%1,%2,%3};"
                 : "+f"(c[0]), "+f"(c[1]), "+f"(c[2]), "+f"(c[3])
                 : "r"(a[0]), "r"(a[1]), "r"(a[2]), "r"(a[3]), "r"(b[0]), "r"(b[1]));
}

// ---------------------------------------------------------------------------
__global__ void reset_kernel() { g_counter = 0; }

// Prep: W_c = m*W_v + (1-m)*W_r -> fp16, pre-swizzled packed chunk images.
__global__ void prep_kernel(const float* __restrict__ Wv, const float* __restrict__ Wr,
                            const float* __restrict__ mix) {
    int gid = blockIdx.x * blockDim.x + threadIdx.x;
    if (gid >= K_DIM * N_DIM) return;
    int n = gid & 511;
    int k = gid >> 9;
    float m = 1.0f / (1.0f + expf(-mix[0]));
    float w = m * Wv[k * N_DIM + n] + (1.0f - m) * Wr[k * N_DIM + n];
    int c  = k >> 5;
    int kk = k & 31;
    uint32_t off = swz((uint32_t)((n >> 1) * 128 + (n & 1) * 64 + kk * 2));
    *(__half*)(&g_Bimg[c][off]) = __float2half(w);
}

// ---------------------------------------------------------------------------
// Persistent fused GEMM (fp16 mma.sync) + relu + LayerNorm(512)
// ---------------------------------------------------------------------------
__global__ void __launch_bounds__(NT, 1)
gemm_ln_kernel(const float* __restrict__ x, const float* __restrict__ gamma,
               const float* __restrict__ beta, float* __restrict__ out) {
    extern __shared__ char smem[];
    const uint32_t sb = smem_u32(smem);
    const int tid  = threadIdx.x;
    const int warp = tid >> 5;
    const int lane = tid & 31;
    const int wm   = warp >> 3;   // 0..1 -> 32-row half
    const int wn   = warp & 7;    // 0..7 -> 64-col slice

    // gamma/beta into smem (once)
    {
        float* gsh = (float*)(smem + SM_GB);
        for (int i = tid; i < N_DIM; i += NT) {
            gsh[i]         = gamma[i];
            gsh[N_DIM + i] = beta[i];
        }
    }

    // Resident B chunks 0..2 (once per CTA lifetime)
    #pragma unroll
    for (int i = 0; i < 12; i++) {
        int j = tid + i * NT;              // 0..6143
        int c = j >> 11;
        int o = (j & 2047) * 16;
        cp16(sb + SM_BRES + c * 32768 + o, &g_Bimg[c][o]);
    }
    cp_commit();
    cp_wait<0>();                          // resident data in-flight done (visible after sync)

    // per-lane ldmatrix base offsets (KC=32 packed layout)
    const uint32_t arow = (uint32_t)((wm * 32 + (lane & 15)) * 128 + (lane >> 4) * 16);
    const int nb = wn * 64 + ((lane >> 4) & 1) * 8 + (lane & 7);
    const uint32_t brow = (uint32_t)((nb >> 1) * 128 + (nb & 1) * 64 + ((lane >> 3) & 1) * 16);

    // A indexing: chunk = 64 rows x 32 f32 = 512 float4; 1 per thread
    const int ar = tid >> 3;
    const int as = tid & 7;
    const uint32_t aso = swz((uint32_t)(ar * 128 + as * 8));

    float* psum  = (float*)(smem + SM_PS);   // [64][8]
    float* psq   = psum + 512;               // [64][8]
    float* stats = psq + 512;                // [64][2]
    const float* gsh = (const float*)(smem + SM_GB);
    const float* bsh = gsh + N_DIM;

    for (;;) {
        // ---- grab next tile ----
        if (tid == 0) *(int*)(smem + SM_T) = atomicAdd(&g_counter, 1);
        __syncthreads();
        const int t = *(int*)(smem + SM_T);
        if (t >= NTILES) break;
        const size_t m0 = (size_t)t * BM;
        const float* xrow = x + (m0 + ar) * K_DIM + as * 4;

        float acc[2][8][4];
        #pragma unroll
        for (int mt = 0; mt < 2; mt++)
            #pragma unroll
            for (int nt = 0; nt < 8; nt++)
                #pragma unroll
                for (int i = 0; i < 4; i++) acc[mt][nt][i] = 0.0f;

        // ---- per-tile A prologue: chunk0 -> st0, chunk1 -> regs ----
        {
            float4 v = *(const float4*)(xrow);
            __half2 h01 = __floats2half2_rn(v.x, v.y);
            __half2 h23 = __floats2half2_rn(v.z, v.w);
            *(uint2*)(smem + SM_A + aso) = make_uint2(*(uint32_t*)&h01, *(uint32_t*)&h23);
        }
        float4 av = *(const float4*)(xrow + KC);

        // ---- k-chunk loop: 0..2 resident, 3..7 streamed (3-stage ring) ----
        // stream commits: c3@i0, c4@i1, c5@i2, c6@i4, c7@i5
        // waits:          i3:wait<2>  i4:wait<1>  i5:wait<1>  i6:wait<1>  i7:wait<0>
        #pragma unroll
        for (int c = 0; c < NCH; c++) {
            if (c == 3) cp_wait<2>();
            else if (c == 4 || c == 5 || c == 6) cp_wait<1>();
            else if (c == 7) cp_wait<0>();
            __syncthreads();

            // A: STS chunk c+1 into other stage, LDG chunk c+2
            if (c < NCH - 1) {
                __half2 h01 = __floats2half2_rn(av.x, av.y);
                __half2 h23 = __floats2half2_rn(av.z, av.w);
                *(uint2*)(smem + SM_A + ((c + 1) & 1) * 8192 + aso) =
                    make_uint2(*(uint32_t*)&h01, *(uint32_t*)&h23);
                if (c < NCH - 2) av = *(const float4*)(xrow + (c + 2) * KC);
            }

            // stream-B issues (compile-time schedule)
            if (c == 0 || c == 1 || c == 2 || c == 4 || c == 5) {
                const int sc = (c < 3) ? (c + 3) : (c + 2);      // chunk being fetched
                const int st = (sc - 3) % 3;                      // ring stage
                #pragma unroll
                for (int i = 0; i < 4; i++) {
                    int j = tid + i * NT;                         // 0..2047
                    cp16(sb + SM_BSTR + st * 32768 + j * 16, &g_Bimg[sc][j * 16]);
                }
                cp_commit();
            }

            // ---- MMA on chunk c ----
            const uint32_t Ab = sb + SM_A + (c & 1) * 8192;
            const uint32_t Bb = (c < NRES) ? (sb + SM_BRES + c * 32768)
                                           : (sb + SM_BSTR + ((c - 3) % 3) * 32768);
            uint32_t af[2][2][4];
            #pragma unroll
            for (int mt = 0; mt < 2; mt++)
                ldsm4(af[0][mt], Ab + swz(arow + mt * 2048));
            #pragma unroll
            for (int ks = 0; ks < 2; ks++) {
                if (ks == 0)
                    #pragma unroll
                    for (int mt = 0; mt < 2; mt++)
                        ldsm4(af[1][mt], Ab + swz(arow + mt * 2048 + 32));
                #pragma unroll
                for (int bt = 0; bt < 4; bt++) {
                    uint32_t bh[4];
                    ldsm4(bh, Bb + swz(brow + bt * 1024 + ks * 32));
                    #pragma unroll
                    for (int mt = 0; mt < 2; mt++) {
                        hmma(acc[mt][2 * bt],     af[ks][mt], &bh[0]);
                        hmma(acc[mt][2 * bt + 1], af[ks][mt], &bh[2]);
                    }
                }
            }
        }

        // ---------------- Epilogue: relu + LayerNorm(512) ----------------
        #pragma unroll
        for (int mt = 0; mt < 2; mt++) {
            #pragma unroll
            for (int half = 0; half < 2; half++) {
                float s = 0.0f, q = 0.0f;
                #pragma unroll
                for (int nt = 0; nt < 8; nt++) {
                    float v0 = fmaxf(acc[mt][nt][half * 2 + 0], 0.0f);
                    float v1 = fmaxf(acc[mt][nt][half * 2 + 1], 0.0f);
                    s += v0 + v1;
                    q += v0 * v0 + v1 * v1;
                }
                s += __shfl_xor_sync(0xFFFFFFFFu, s, 1);
                q += __shfl_xor_sync(0xFFFFFFFFu, q, 1);
                s += __shfl_xor_sync(0xFFFFFFFFu, s, 2);
                q += __shfl_xor_sync(0xFFFFFFFFu, q, 2);
                if ((lane & 3) == 0) {
                    int r = wm * 32 + mt * 16 + (lane >> 2) + half * 8;
                    psum[r * 8 + wn] = s;
                    psq[r * 8 + wn]  = q;
                }
            }
        }
        __syncthreads();
        if (tid < BM) {
            float st = 0.0f, qt = 0.0f;
            #pragma unroll
            for (int i = 0; i < 8; i++) { st += psum[tid * 8 + i]; qt += psq[tid * 8 + i]; }
            float mean = st * (1.0f / 512.0f);
            float var  = qt * (1.0f / 512.0f) - mean * mean;
            stats[tid * 2]     = mean;
            stats[tid * 2 + 1] = rsqrtf(var + 1e-5f);
        }
        __syncthreads();

        #pragma unroll
        for (int mt = 0; mt < 2; mt++) {
            #pragma unroll
            for (int half = 0; half < 2; half++) {
                int r = wm * 32 + mt * 16 + (lane >> 2) + half * 8;
                float mean = stats[r * 2];
                float rstd = stats[r * 2 + 1];
                float* orow = out + (size_t)(m0 + r) * N_DIM;
                #pragma unroll
                for (int nt = 0; nt < 8; nt++) {
                    int col = wn * 64 + nt * 8 + (lane & 3) * 2;
                    float2 o;
                    o.x = (fmaxf(acc[mt][nt][half * 2 + 0], 0.0f) - mean) * rstd * gsh[col]     + bsh[col];
                    o.y = (fmaxf(acc[mt][nt][half * 2 + 1], 0.0f) - mean) * rstd * gsh[col + 1] + bsh[col + 1];
                    *(float2*)(orow + col) = o;
                }
            }
        }
        // next iteration's post-atomic __syncthreads orders smem reuse
    }
}

// ---------------------------------------------------------------------------
// Host launcher. Inputs: x, W_q, W_k, W_v, W_r, mix, gamma, beta
// ---------------------------------------------------------------------------
extern "C" void kernel_launch(void* const* d_in, const int* in_sizes, int n_in,
                              void* d_out, int out_size) {
    const float* x     = (const float*)d_in[0];
    const float* Wv    = (const float*)d_in[3];
    const float* Wr    = (const float*)d_in[4];
    const float* mix   = (const float*)d_in[5];
    const float* gamma = (const float*)d_in[6];
    const float* beta  = (const float*)d_in[7];
    float* out = (float*)d_out;

    cudaFuncSetAttribute(gemm_ln_kernel, cudaFuncAttributeMaxDynamicSharedMemorySize, SMEM_TOTAL);

    reset_kernel<<<1, 1>>>();
    prep_kernel<<<(K_DIM * N_DIM + 255) / 256, 256>>>(Wv, Wr, mix);
    gemm_ln_kernel<<<GRID, NT, SMEM_TOTAL>>>(x, gamma, beta, out);
}